// round 9
// baseline (speedup 1.0000x reference)
#include <cuda_runtime.h>
#include <cuda_bf16.h>
#include <math.h>
#include <stdint.h>

#define D_MODEL 256
#define NHEAD   8
#define HEAD_DIM 32
#define B_SZ    4
#define N_SZ    256

// ---------------- device scratch ----------------
__device__ float g_Wt[D_MODEL * D_MODEL];
__device__ float g_node_p[B_SZ * N_SZ * D_MODEL];
__device__ float g_out0[B_SZ * N_SZ * D_MODEL];
__device__ __align__(128) unsigned char g_WB_hi[131072];
__device__ __align__(128) unsigned char g_WB_lo[131072];

__device__ __forceinline__ uint32_t smem_u32(const void* p) {
    uint32_t a;
    asm("{ .reg .u64 t; cvta.to.shared.u64 t, %1; cvt.u32.u64 %0, t; }" : "=r"(a) : "l"(p));
    return a;
}

__device__ __forceinline__ void ldsm_x4(uint32_t r[4], uint32_t addr) {
    asm volatile("ldmatrix.sync.aligned.m8n8.x4.shared.b16 {%0,%1,%2,%3}, [%4];"
                 : "=r"(r[0]), "=r"(r[1]), "=r"(r[2]), "=r"(r[3]) : "r"(addr));
}

__device__ __forceinline__ void mma_bf16(float c[4], const uint32_t a[4], const uint32_t b[2]) {
    asm volatile(
        "mma.sync.aligned.m16n8k16.row.col.f32.bf16.bf16.f32 "
        "{%0,%1,%2,%3}, {%4,%5,%6,%7}, {%8,%9}, {%0,%1,%2,%3};"
        : "+f"(c[0]), "+f"(c[1]), "+f"(c[2]), "+f"(c[3])
        : "r"(a[0]), "r"(a[1]), "r"(a[2]), "r"(a[3]), "r"(b[0]), "r"(b[1]));
}

#define MBAR_INIT(mbar, cnt) \
    asm volatile("mbarrier.init.shared.b64 [%0], %1;" :: "r"((uint32_t)(mbar)), "r"((uint32_t)(cnt)) : "memory")
#define MBAR_EXPECT_TX(mbar, tx) \
    asm volatile("mbarrier.arrive.expect_tx.shared.b64 _, [%0], %1;" :: "r"((uint32_t)(mbar)), "r"((uint32_t)(tx)) : "memory")
#define MBAR_WAIT(mbar, parity) do {                                          \
    uint32_t _m = (uint32_t)(mbar); uint32_t _p = (uint32_t)(parity);         \
    asm volatile(                                                             \
        "{\n\t.reg .pred P1;\n\t"                                             \
        "WAIT_LOOP_%=:\n\t"                                                   \
        "mbarrier.try_wait.parity.acquire.cta.shared::cta.b64 P1, [%0], %1, 0x989680;\n\t" \
        "@P1 bra.uni WAIT_DONE_%=;\n\t"                                       \
        "bra.uni WAIT_LOOP_%=;\n\t"                                           \
        "WAIT_DONE_%=:\n\t}"                                                  \
        :: "r"(_m), "r"(_p) : "memory");                                      \
} while (0)
#define BULK_G2S(dst, src, bytes, mbar) \
    asm volatile("cp.async.bulk.shared::cta.global.mbarrier::complete_tx::bytes [%0], [%1], %2, [%3];" \
                 :: "r"((uint32_t)(dst)), "l"(src), "r"((uint32_t)(bytes)), "r"((uint32_t)(mbar)) : "memory")

// ---------------- prep kernels (R1-R3 proven split) ----------------
__global__ void transpose_kernel(const float* __restrict__ W) {
    int o = blockIdx.x * 256 + threadIdx.x;  // o = k*256 + d
    int k = o >> 8, d = o & 255;
    g_Wt[o] = W[d * 256 + k];
}

__global__ void wprep_kernel(const float* __restrict__ W) {
    int idx = blockIdx.x * 256 + threadIdx.x;  // d*256 + k
    int d = idx >> 8, k = idx & 255;
    float w = W[idx];
    __nv_bfloat16 h = __float2bfloat16_rn(w);
    float r = w - __bfloat162float(h);
    __nv_bfloat16 l = __float2bfloat16_rn(r);
    int chunk = k >> 6, kc = k & 63;
    int off = d * 128 + kc * 2;
    int sw = off ^ ((off >> 3) & 0x70);
    int pos = chunk * 32768 + sw;
    *(unsigned short*)(g_WB_hi + pos) = __bfloat16_as_ushort(h);
    *(unsigned short*)(g_WB_lo + pos) = __bfloat16_as_ushort(l);
}

// ---------------- fp32 tile GEMM for small projections (R6 exact) ----------------
__device__ __forceinline__ void gemm_tile(const float* __restrict__ A, float acc[8][8]) {
    const int tid = threadIdx.x;
    const int tx = tid & 31;
    const int ty = tid >> 5;

    __shared__ float As[2][16][65];
    __shared__ float Ws[2][16][260];

#pragma unroll
    for (int a = 0; a < 8; a++)
#pragma unroll
        for (int c = 0; c < 8; c++) acc[a][c] = 0.0f;

    const int rowL = tid >> 2;
    const int kq = tid & 3;

    {
        float4 v = *(const float4*)(A + rowL * 256 + kq * 4);
        As[0][kq * 4 + 0][rowL] = v.x;
        As[0][kq * 4 + 1][rowL] = v.y;
        As[0][kq * 4 + 2][rowL] = v.z;
        As[0][kq * 4 + 3][rowL] = v.w;
#pragma unroll
        for (int c = 0; c < 4; c++) {
            int f = c * 256 + tid;
            int kk = f >> 6, d4 = f & 63;
            *(float4*)&Ws[0][kk][d4 * 4] = *(const float4*)(g_Wt + kk * 256 + d4 * 4);
        }
    }
    __syncthreads();

#pragma unroll 1
    for (int kt = 0; kt < 16; kt++) {
        const int cur = kt & 1;
        if (kt < 15) {
            const int nxt = cur ^ 1;
            const int k0 = (kt + 1) * 16;
            float4 v = *(const float4*)(A + rowL * 256 + k0 + kq * 4);
            As[nxt][kq * 4 + 0][rowL] = v.x;
            As[nxt][kq * 4 + 1][rowL] = v.y;
            As[nxt][kq * 4 + 2][rowL] = v.z;
            As[nxt][kq * 4 + 3][rowL] = v.w;
#pragma unroll
            for (int c = 0; c < 4; c++) {
                int f = c * 256 + tid;
                int kk = f >> 6, d4 = f & 63;
                *(float4*)&Ws[nxt][kk][d4 * 4] = *(const float4*)(g_Wt + (k0 + kk) * 256 + d4 * 4);
            }
        }
#pragma unroll
        for (int kk = 0; kk < 16; kk++) {
            float a[8], w[8];
#pragma unroll
            for (int jj = 0; jj < 8; jj++) a[jj] = As[cur][kk][jj * 8 + ty];
#pragma unroll
            for (int u = 0; u < 8; u++) w[u] = Ws[cur][kk][u * 32 + tx];
#pragma unroll
            for (int jj = 0; jj < 8; jj++)
#pragma unroll
                for (int u = 0; u < 8; u++)
                    acc[jj][u] = fmaf(a[jj], w[u], acc[jj][u]);
        }
        __syncthreads();
    }
}

__global__ void __launch_bounds__(256, 2)
proj_nodes_kernel(const float* __restrict__ nodes, const float* __restrict__ bias) {
    float acc[8][8];
    gemm_tile(nodes + (size_t)blockIdx.x * 64 * 256, acc);
    const int tx = threadIdx.x & 31, ty = threadIdx.x >> 5;
#pragma unroll
    for (int jj = 0; jj < 8; jj++) {
        int r = blockIdx.x * 64 + jj * 8 + ty;
#pragma unroll
        for (int u = 0; u < 8; u++)
            g_node_p[r * 256 + u * 32 + tx] = acc[jj][u] + bias[u * 32 + tx];
    }
}

__global__ void __launch_bounds__(256, 2)
proj_final_kernel(const float* __restrict__ bias, float* __restrict__ out) {
    float acc[8][8];
    gemm_tile(g_out0 + (size_t)blockIdx.x * 64 * 256, acc);
    const int tx = threadIdx.x & 31, ty = threadIdx.x >> 5;
#pragma unroll
    for (int jj = 0; jj < 8; jj++) {
        int r = blockIdx.x * 64 + jj * 8 + ty;
#pragma unroll
        for (int u = 0; u < 8; u++)
            out[r * 256 + u * 32 + tx] = acc[jj][u] + bias[u * 32 + tx];
    }
}

// ---------------- edge projection + scores (R6 exact) ----------------
#define SM_A   0
#define SM_W   65536
#define SM_DYN 196608
#define NTHR   512

__device__ __forceinline__ void cvt_store_a(char* sm, int slot, int flat, float4 v) {
    __nv_bfloat16 hx = __float2bfloat16_rn(v.x);
    __nv_bfloat16 hy = __float2bfloat16_rn(v.y);
    __nv_bfloat16 hz = __float2bfloat16_rn(v.z);
    __nv_bfloat16 hw = __float2bfloat16_rn(v.w);
    __nv_bfloat16 lx = __float2bfloat16_rn(v.x - __bfloat162float(hx));
    __nv_bfloat16 ly = __float2bfloat16_rn(v.y - __bfloat162float(hy));
    __nv_bfloat16 lz = __float2bfloat16_rn(v.z - __bfloat162float(hz));
    __nv_bfloat16 lw = __float2bfloat16_rn(v.w - __bfloat162float(hw));
    uint2 hi2, lo2;
    hi2.x = (uint32_t)__bfloat16_as_ushort(hx) | ((uint32_t)__bfloat16_as_ushort(hy) << 16);
    hi2.y = (uint32_t)__bfloat16_as_ushort(hz) | ((uint32_t)__bfloat16_as_ushort(hw) << 16);
    lo2.x = (uint32_t)__bfloat16_as_ushort(lx) | ((uint32_t)__bfloat16_as_ushort(ly) << 16);
    lo2.y = (uint32_t)__bfloat16_as_ushort(lz) | ((uint32_t)__bfloat16_as_ushort(lw) << 16);
    int row = flat >> 4, c4 = flat & 15;
    int off = row * 128 + c4 * 8;
    int sw = off ^ ((off >> 3) & 0x70);
    char* base = sm + SM_A + slot * 32768;
    *(uint2*)(base + sw) = hi2;
    *(uint2*)(base + 16384 + sw) = lo2;
}

__global__ void __launch_bounds__(NTHR, 1)
edge_score_mma(const float* __restrict__ edges, const float* __restrict__ bias,
               float* __restrict__ scores) {
    extern __shared__ char sm[];
    __shared__ __align__(8) unsigned long long mbarr[2];
    const uint32_t smb = smem_u32(sm);
    const uint32_t mb0 = smem_u32(&mbarr[0]);
    const int tid = threadIdx.x, wid = tid >> 5, lane = tid & 31;
    const int jt = blockIdx.x, i = blockIdx.y, b = blockIdx.z;
    const int wm = (wid >> 3) * 64;
    const int wn = (wid & 7) * 32;

    const float* A = edges + ((((size_t)b * N_SZ + i) * N_SZ) + (size_t)jt * 128) * D_MODEL;
    const unsigned long long gwh = (unsigned long long)__cvta_generic_to_global(g_WB_hi);
    const unsigned long long gwl = (unsigned long long)__cvta_generic_to_global(g_WB_lo);

    if (tid == 0) {
        MBAR_INIT(mb0, 1);
        MBAR_INIT(mb0 + 8, 1);
    }
    __syncthreads();

    if (tid == 0) {
        MBAR_EXPECT_TX(mb0, 65536);
        BULK_G2S(smb + SM_W, gwh, 32768, mb0);
        BULK_G2S(smb + SM_W + 32768, gwl, 32768, mb0);
    }
#pragma unroll
    for (int q = 0; q < 4; q++) {
        int flat = q * NTHR + tid;
        int row = flat >> 4, c4 = flat & 15;
        float4 v = *(const float4*)(A + (size_t)row * 256 + c4 * 4);
        cvt_store_a(sm, 0, flat, v);
    }
    __syncthreads();

    float acc[4][4][4];
#pragma unroll
    for (int mf = 0; mf < 4; mf++)
#pragma unroll
        for (int nf = 0; nf < 4; nf++)
#pragma unroll
            for (int c = 0; c < 4; c++) acc[mf][nf][c] = 0.0f;

    uint32_t apre[4], axor[4];
#pragma unroll
    for (int mf = 0; mf < 4; mf++) {
        int row = wm + mf * 16 + (lane & 15);
        apre[mf] = row * 128;
        axor[mf] = (row & 7) << 4;
    }
    const int koffA = (lane >> 4) * 8;
    uint32_t bpre[2], bxor[2];
#pragma unroll
    for (int gb = 0; gb < 2; gb++) {
        int n = wn + gb * 16 + (((lane >> 3) >= 2) ? 8 : 0) + (lane & 7);
        bpre[gb] = n * 128;
        bxor[gb] = (n & 7) << 4;
    }
    const int kcB = ((lane >> 3) & 1) * 8;

#pragma unroll 1
    for (int ch = 0; ch < 4; ch++) {
        const int cur = ch & 1, nxt = cur ^ 1;
        if (ch < 3 && tid == 0) {
            MBAR_EXPECT_TX(mb0 + 8 * nxt, 65536);
            BULK_G2S(smb + SM_W + nxt * 65536, gwh + (ch + 1) * 32768, 32768, mb0 + 8 * nxt);
            BULK_G2S(smb + SM_W + nxt * 65536 + 32768, gwl + (ch + 1) * 32768, 32768, mb0 + 8 * nxt);
        }
        float4 v[4];
        if (ch < 3) {
            const float* Anext = A + (ch + 1) * 64;
#pragma unroll
            for (int q = 0; q < 4; q++) {
                int flat = q * NTHR + tid;
                v[q] = *(const float4*)(Anext + (size_t)(flat >> 4) * 256 + (flat & 15) * 4);
            }
        }
        MBAR_WAIT(mb0 + 8 * cur, ch >> 1);

        const uint32_t abase = smb + SM_A + cur * 32768;
        const uint32_t wbase = smb + SM_W + cur * 65536;
#pragma unroll
        for (int ks = 0; ks < 4; ks++) {
            const uint32_t kc2 = (uint32_t)((ks * 16 + kcB) * 2);
            uint32_t bh[2][4], bl[2][4];
#pragma unroll
            for (int gb = 0; gb < 2; gb++) {
                uint32_t bd = wbase + bpre[gb] + (kc2 ^ bxor[gb]);
                ldsm_x4(bh[gb], bd);
                ldsm_x4(bl[gb], bd + 32768);
            }
            const uint32_t kg2 = (uint32_t)((ks * 16 + koffA) * 2);
#pragma unroll
            for (int mf = 0; mf < 4; mf++) {
                uint32_t ah[4], al[4];
                uint32_t ad = abase + apre[mf] + (kg2 ^ axor[mf]);
                ldsm_x4(ah, ad);
                ldsm_x4(al, ad + 16384);
#pragma unroll
                for (int nf = 0; nf < 4; nf++) {
                    const uint32_t* ph = &bh[nf >> 1][(nf & 1) * 2];
                    const uint32_t* pl = &bl[nf >> 1][(nf & 1) * 2];
                    mma_bf16(acc[mf][nf], ah, ph);
                    mma_bf16(acc[mf][nf], ah, pl);
                    mma_bf16(acc[mf][nf], al, ph);
                }
            }
        }
        if (ch < 3) {
#pragma unroll
            for (int q = 0; q < 4; q++)
                cvt_store_a(sm, nxt, q * NTHR + tid, v[q]);
        }
        __syncthreads();
    }

    // ---- epilogue ----
    {
        float* nps = (float*)sm;
        const float* src = g_node_p + ((size_t)b * N_SZ + jt * 128) * 256;
        int row = tid >> 2, q4 = tid & 3;
        const float4* s4 = (const float4*)(src + (size_t)row * 256) + q4 * 16;
        float4* d4 = (float4*)(nps + row * 260) + q4 * 16;
#pragma unroll
        for (int q = 0; q < 16; q++) d4[q] = s4[q];
    }
    __syncthreads();

    float pb[8], p1[8];
    {
        const float* npi = g_node_p + ((size_t)b * N_SZ + i) * 256;
#pragma unroll
        for (int nf = 0; nf < 4; nf++)
#pragma unroll
            for (int v2 = 0; v2 < 2; v2++) {
                int idx = nf * 2 + v2;
                int d = wn + nf * 8 + (lane & 3) * 2 + v2;
                float bv = bias[d];
                pb[idx] = bv;
                p1[idx] = bv + npi[d];
            }
    }

    const int hg = wid & 7;
    const float* nps = (const float*)sm;
#pragma unroll
    for (int mf = 0; mf < 4; mf++) {
#pragma unroll
        for (int half = 0; half < 2; half++) {
            int r = wm + mf * 16 + (lane >> 2) + half * 8;
            const float* nj = nps + r * 260 + wn;
            float s = 0.0f;
#pragma unroll
            for (int nf = 0; nf < 4; nf++)
#pragma unroll
                for (int v2 = 0; v2 < 2; v2++) {
                    int idx = nf * 2 + v2;
                    float a = acc[mf][nf][half * 2 + v2];
                    float njv = nj[nf * 8 + (lane & 3) * 2 + v2];
                    s += (a + p1[idx]) * (a + pb[idx] + njv);
                }
            s += __shfl_xor_sync(0xffffffffu, s, 1);
            s += __shfl_xor_sync(0xffffffffu, s, 2);
            if ((lane & 3) == 0) {
                scores[((((size_t)b * NHEAD + hg) * N_SZ + i) << 8) + jt * 128 + r] =
                    10.0f * tanhf(s * 0.17677669529663687f);
            }
        }
    }
}

// ---------------- softmax + AV (R6 exact) ----------------
__global__ void softmax_av_kernel(float* __restrict__ attn) {
    const int i = blockIdx.x, h = blockIdx.y, b = blockIdx.z;
    const int tid = threadIdx.x;
    float* row = attn + ((((size_t)(b * NHEAD + h) * N_SZ) + i) << 8);

    __shared__ float sh[16];
    __shared__ float ps[256];
    __shared__ float red[8][33];

    float s = row[tid];
    float m = s;
#pragma unroll
    for (int off = 16; off > 0; off >>= 1)
        m = fmaxf(m, __shfl_xor_sync(0xffffffffu, m, off));
    if ((tid & 31) == 0) sh[tid >> 5] = m;
    __syncthreads();
    float bm = sh[0];
#pragma unroll
    for (int g = 1; g < 8; g++) bm = fmaxf(bm, sh[g]);

    float p = __expf(s - bm);
    float t = p;
#pragma unroll
    for (int off = 16; off > 0; off >>= 1)
        t += __shfl_xor_sync(0xffffffffu, t, off);
    if ((tid & 31) == 0) sh[8 + (tid >> 5)] = t;
    __syncthreads();
    float sum = 0.0f;
#pragma unroll
    for (int g = 0; g < 8; g++) sum += sh[8 + g];

    float a = p * (1.0f / sum);
    row[tid] = a;
    ps[tid] = a;
    __syncthreads();

    const int d = tid & 31, g = tid >> 5;
    const float* np = g_node_p + (size_t)b * N_SZ * D_MODEL + h * 32 + d;
    float acc = 0.0f;
#pragma unroll
    for (int jj = 0; jj < 32; jj++) {
        int j = g * 32 + jj;
        acc = fmaf(ps[j], np[(size_t)j * 256], acc);
    }
    red[g][d] = acc;
    __syncthreads();
    if (tid < 32) {
        float o = 0.0f;
#pragma unroll
        for (int g2 = 0; g2 < 8; g2++) o += red[g2][tid];
        g_out0[((size_t)(b * N_SZ + i)) * D_MODEL + h * 32 + tid] = o;
    }
}

// ---------------- launch (R3 structure: edge at index 3) ----------------
extern "C" void kernel_launch(void* const* d_in, const int* in_sizes, int n_in,
                              void* d_out, int out_size) {
    const float* nodes = (const float*)d_in[0];
    const float* edges = (const float*)d_in[1];
    const float* W     = (const float*)d_in[2];
    const float* bias  = (const float*)d_in[3];

    float* out  = (float*)d_out;
    float* attn = out + B_SZ * N_SZ * D_MODEL;

    cudaFuncSetAttribute(edge_score_mma, cudaFuncAttributeMaxDynamicSharedMemorySize, SM_DYN);

    transpose_kernel<<<256, 256>>>(W);                        // 0
    wprep_kernel<<<256, 256>>>(W);                            // 1
    proj_nodes_kernel<<<(B_SZ * N_SZ) / 64, 256>>>(nodes, bias);  // 2
    dim3 g2(2, N_SZ, B_SZ);
    edge_score_mma<<<g2, NTHR, SM_DYN>>>(edges, bias, attn);  // 3
    dim3 g3(N_SZ, NHEAD, B_SZ);
    softmax_av_kernel<<<g3, 256>>>(attn);                     // 4
    proj_final_kernel<<<(B_SZ * N_SZ) / 64, 256>>>(bias, out);    // 5
}

// round 10
// speedup vs baseline: 1.0350x; 1.0350x over previous
#include <cuda_runtime.h>
#include <cuda_bf16.h>
#include <math.h>
#include <stdint.h>

#define D_MODEL 256
#define NHEAD   8
#define HEAD_DIM 32
#define B_SZ    4
#define N_SZ    256

// ---------------- device scratch ----------------
__device__ float g_Wt[D_MODEL * D_MODEL];
__device__ float g_node_p[B_SZ * N_SZ * D_MODEL];
__device__ float g_out0[B_SZ * N_SZ * D_MODEL];
__device__ __align__(128) unsigned char g_WB_hi[131072];
__device__ __align__(128) unsigned char g_WB_lo[131072];

__device__ __forceinline__ uint32_t smem_u32(const void* p) {
    uint32_t a;
    asm("{ .reg .u64 t; cvta.to.shared.u64 t, %1; cvt.u32.u64 %0, t; }" : "=r"(a) : "l"(p));
    return a;
}

__device__ __forceinline__ void ldsm_x4(uint32_t r[4], uint32_t addr) {
    asm volatile("ldmatrix.sync.aligned.m8n8.x4.shared.b16 {%0,%1,%2,%3}, [%4];"
                 : "=r"(r[0]), "=r"(r[1]), "=r"(r[2]), "=r"(r[3]) : "r"(addr));
}

__device__ __forceinline__ void mma_bf16(float c[4], const uint32_t a[4], const uint32_t b[2]) {
    asm volatile(
        "mma.sync.aligned.m16n8k16.row.col.f32.bf16.bf16.f32 "
        "{%0,%1,%2,%3}, {%4,%5,%6,%7}, {%8,%9}, {%0,%1,%2,%3};"
        : "+f"(c[0]), "+f"(c[1]), "+f"(c[2]), "+f"(c[3])
        : "r"(a[0]), "r"(a[1]), "r"(a[2]), "r"(a[3]), "r"(b[0]), "r"(b[1]));
}

#define MBAR_INIT(mbar, cnt) \
    asm volatile("mbarrier.init.shared.b64 [%0], %1;" :: "r"((uint32_t)(mbar)), "r"((uint32_t)(cnt)) : "memory")
#define MBAR_EXPECT_TX(mbar, tx) \
    asm volatile("mbarrier.arrive.expect_tx.shared.b64 _, [%0], %1;" :: "r"((uint32_t)(mbar)), "r"((uint32_t)(tx)) : "memory")
#define MBAR_WAIT(mbar, parity) do {                                          \
    uint32_t _m = (uint32_t)(mbar); uint32_t _p = (uint32_t)(parity);         \
    asm volatile(                                                             \
        "{\n\t.reg .pred P1;\n\t"                                             \
        "WAIT_LOOP_%=:\n\t"                                                   \
        "mbarrier.try_wait.parity.acquire.cta.shared::cta.b64 P1, [%0], %1, 0x989680;\n\t" \
        "@P1 bra.uni WAIT_DONE_%=;\n\t"                                       \
        "bra.uni WAIT_LOOP_%=;\n\t"                                           \
        "WAIT_DONE_%=:\n\t}"                                                  \
        :: "r"(_m), "r"(_p) : "memory");                                      \
} while (0)
#define BULK_G2S(dst, src, bytes, mbar) \
    asm volatile("cp.async.bulk.shared::cta.global.mbarrier::complete_tx::bytes [%0], [%1], %2, [%3];" \
                 :: "r"((uint32_t)(dst)), "l"(src), "r"((uint32_t)(bytes)), "r"((uint32_t)(mbar)) : "memory")

// ---------------- prep kernels ----------------
__global__ void transpose_kernel(const float* __restrict__ W) {
    int o = blockIdx.x * 256 + threadIdx.x;  // o = k*256 + d
    int k = o >> 8, d = o & 255;
    g_Wt[o] = W[d * 256 + k];
}

__global__ void wprep_kernel(const float* __restrict__ W) {
    int idx = blockIdx.x * 256 + threadIdx.x;  // d*256 + k
    int d = idx >> 8, k = idx & 255;
    float w = W[idx];
    __nv_bfloat16 h = __float2bfloat16_rn(w);
    float r = w - __bfloat162float(h);
    __nv_bfloat16 l = __float2bfloat16_rn(r);
    int chunk = k >> 6, kc = k & 63;
    int off = d * 128 + kc * 2;
    int sw = off ^ ((off >> 3) & 0x70);
    int pos = chunk * 32768 + sw;
    *(unsigned short*)(g_WB_hi + pos) = __bfloat16_as_ushort(h);
    *(unsigned short*)(g_WB_lo + pos) = __bfloat16_as_ushort(l);
}

// ---------------- fp32 tile GEMM for small projections (R6 exact) ----------------
__device__ __forceinline__ void gemm_tile(const float* __restrict__ A, float acc[8][8]) {
    const int tid = threadIdx.x;
    const int tx = tid & 31;
    const int ty = tid >> 5;

    __shared__ float As[2][16][65];
    __shared__ float Ws[2][16][260];

#pragma unroll
    for (int a = 0; a < 8; a++)
#pragma unroll
        for (int c = 0; c < 8; c++) acc[a][c] = 0.0f;

    const int rowL = tid >> 2;
    const int kq = tid & 3;

    {
        float4 v = *(const float4*)(A + rowL * 256 + kq * 4);
        As[0][kq * 4 + 0][rowL] = v.x;
        As[0][kq * 4 + 1][rowL] = v.y;
        As[0][kq * 4 + 2][rowL] = v.z;
        As[0][kq * 4 + 3][rowL] = v.w;
#pragma unroll
        for (int c = 0; c < 4; c++) {
            int f = c * 256 + tid;
            int kk = f >> 6, d4 = f & 63;
            *(float4*)&Ws[0][kk][d4 * 4] = *(const float4*)(g_Wt + kk * 256 + d4 * 4);
        }
    }
    __syncthreads();

#pragma unroll 1
    for (int kt = 0; kt < 16; kt++) {
        const int cur = kt & 1;
        if (kt < 15) {
            const int nxt = cur ^ 1;
            const int k0 = (kt + 1) * 16;
            float4 v = *(const float4*)(A + rowL * 256 + k0 + kq * 4);
            As[nxt][kq * 4 + 0][rowL] = v.x;
            As[nxt][kq * 4 + 1][rowL] = v.y;
            As[nxt][kq * 4 + 2][rowL] = v.z;
            As[nxt][kq * 4 + 3][rowL] = v.w;
#pragma unroll
            for (int c = 0; c < 4; c++) {
                int f = c * 256 + tid;
                int kk = f >> 6, d4 = f & 63;
                *(float4*)&Ws[nxt][kk][d4 * 4] = *(const float4*)(g_Wt + (k0 + kk) * 256 + d4 * 4);
            }
        }
#pragma unroll
        for (int kk = 0; kk < 16; kk++) {
            float a[8], w[8];
#pragma unroll
            for (int jj = 0; jj < 8; jj++) a[jj] = As[cur][kk][jj * 8 + ty];
#pragma unroll
            for (int u = 0; u < 8; u++) w[u] = Ws[cur][kk][u * 32 + tx];
#pragma unroll
            for (int jj = 0; jj < 8; jj++)
#pragma unroll
                for (int u = 0; u < 8; u++)
                    acc[jj][u] = fmaf(a[jj], w[u], acc[jj][u]);
        }
        __syncthreads();
    }
}

__global__ void __launch_bounds__(256, 2)
proj_nodes_kernel(const float* __restrict__ nodes, const float* __restrict__ bias) {
    float acc[8][8];
    gemm_tile(nodes + (size_t)blockIdx.x * 64 * 256, acc);
    const int tx = threadIdx.x & 31, ty = threadIdx.x >> 5;
#pragma unroll
    for (int jj = 0; jj < 8; jj++) {
        int r = blockIdx.x * 64 + jj * 8 + ty;
#pragma unroll
        for (int u = 0; u < 8; u++)
            g_node_p[r * 256 + u * 32 + tx] = acc[jj][u] + bias[u * 32 + tx];
    }
}

__global__ void __launch_bounds__(256, 2)
proj_final_kernel(const float* __restrict__ bias, float* __restrict__ out) {
    float acc[8][8];
    gemm_tile(g_out0 + (size_t)blockIdx.x * 64 * 256, acc);
    const int tx = threadIdx.x & 31, ty = threadIdx.x >> 5;
#pragma unroll
    for (int jj = 0; jj < 8; jj++) {
        int r = blockIdx.x * 64 + jj * 8 + ty;
#pragma unroll
        for (int u = 0; u < 8; u++)
            out[r * 256 + u * 32 + tx] = acc[jj][u] + bias[u * 32 + tx];
    }
}

// ---------------- edge projection + scores: 256 thr, 64-row tile, 2 CTAs/SM ----------------
// SMEM: A slots: 2 x (8KB hi + 8KB lo)  @ 0       (32KB)
//       W chunk (single): 32KB hi + 32KB lo @ 32768 (64KB)
#define SM_A   0
#define SM_W   32768
#define SM_DYN 98304
#define NTHR   256

// convert one float4 (64-row tile): off = row*128 + c4*8
__device__ __forceinline__ void cvt_store_a(char* sm, int slot, int flat, float4 v) {
    __nv_bfloat16 hx = __float2bfloat16_rn(v.x);
    __nv_bfloat16 hy = __float2bfloat16_rn(v.y);
    __nv_bfloat16 hz = __float2bfloat16_rn(v.z);
    __nv_bfloat16 hw = __float2bfloat16_rn(v.w);
    __nv_bfloat16 lx = __float2bfloat16_rn(v.x - __bfloat162float(hx));
    __nv_bfloat16 ly = __float2bfloat16_rn(v.y - __bfloat162float(hy));
    __nv_bfloat16 lz = __float2bfloat16_rn(v.z - __bfloat162float(hz));
    __nv_bfloat16 lw = __float2bfloat16_rn(v.w - __bfloat162float(hw));
    uint2 hi2, lo2;
    hi2.x = (uint32_t)__bfloat16_as_ushort(hx) | ((uint32_t)__bfloat16_as_ushort(hy) << 16);
    hi2.y = (uint32_t)__bfloat16_as_ushort(hz) | ((uint32_t)__bfloat16_as_ushort(hw) << 16);
    lo2.x = (uint32_t)__bfloat16_as_ushort(lx) | ((uint32_t)__bfloat16_as_ushort(ly) << 16);
    lo2.y = (uint32_t)__bfloat16_as_ushort(lz) | ((uint32_t)__bfloat16_as_ushort(lw) << 16);
    int row = flat >> 4, c4 = flat & 15;
    int off = row * 128 + c4 * 8;
    int sw = off ^ ((off >> 3) & 0x70);
    char* base = sm + SM_A + slot * 16384;
    *(uint2*)(base + sw) = hi2;
    *(uint2*)(base + 8192 + sw) = lo2;
}

__global__ void __launch_bounds__(NTHR, 2)
edge_score_mma(const float* __restrict__ edges, const float* __restrict__ bias,
               float* __restrict__ scores) {
    extern __shared__ char sm[];
    __shared__ __align__(8) unsigned long long mbarr[1];
    const uint32_t smb = smem_u32(sm);
    const uint32_t mb0 = smem_u32(&mbarr[0]);
    const int tid = threadIdx.x, wid = tid >> 5, lane = tid & 31;
    const int jt = blockIdx.x, i = blockIdx.y, b = blockIdx.z;
    const int wm = (wid >> 2) * 32;       // 2 m-groups of 32 rows
    const int wn = (wid & 3) * 64;        // 4 n-groups of 64 cols (2 heads each)

    const float* A = edges + ((((size_t)b * N_SZ + i) * N_SZ) + (size_t)jt * 64) * D_MODEL;
    const unsigned long long gwh = (unsigned long long)__cvta_generic_to_global(g_WB_hi);
    const unsigned long long gwl = (unsigned long long)__cvta_generic_to_global(g_WB_lo);

    if (tid == 0) MBAR_INIT(mb0, 1);
    __syncthreads();

    // ---- prologue: W chunk 0 (bulk) + A chunk 0 (convert) ----
    if (tid == 0) {
        MBAR_EXPECT_TX(mb0, 65536);
        BULK_G2S(smb + SM_W, gwh, 32768, mb0);
        BULK_G2S(smb + SM_W + 32768, gwl, 32768, mb0);
    }
#pragma unroll
    for (int q = 0; q < 4; q++) {
        int flat = q * NTHR + tid;               // 1024 float4 over 64 rows x 16 c4
        float4 v = *(const float4*)(A + (size_t)(flat >> 4) * 256 + (flat & 15) * 4);
        cvt_store_a(sm, 0, flat, v);
    }
    __syncthreads();

    float acc[2][8][4];
#pragma unroll
    for (int mf = 0; mf < 2; mf++)
#pragma unroll
        for (int nf = 0; nf < 8; nf++)
#pragma unroll
            for (int c = 0; c < 4; c++) acc[mf][nf][c] = 0.0f;

    uint32_t apre[2], axor[2];
#pragma unroll
    for (int mf = 0; mf < 2; mf++) {
        int row = wm + mf * 16 + (lane & 15);
        apre[mf] = row * 128;
        axor[mf] = (row & 7) << 4;
    }
    const int koffA = (lane >> 4) * 8;
    uint32_t bpre[4], bxor[4];
#pragma unroll
    for (int gb = 0; gb < 4; gb++) {
        int n = wn + gb * 16 + (((lane >> 3) >= 2) ? 8 : 0) + (lane & 7);
        bpre[gb] = n * 128;
        bxor[gb] = (n & 7) << 4;
    }
    const int kcB = ((lane >> 3) & 1) * 8;

#pragma unroll 1
    for (int ch = 0; ch < 4; ch++) {
        const int cur = ch & 1, nxt = cur ^ 1;
        MBAR_WAIT(mb0, ch & 1);                  // W chunk ch ready
        const uint32_t abase = smb + SM_A + cur * 16384;
        const uint32_t wbase = smb + SM_W;

#pragma unroll
        for (int ks = 0; ks < 4; ks++) {
            // prefetch next-chunk A fp32 (1 float4/thread/ks)
            float4 v0;
            int f0 = ks * NTHR + tid;
            if (ch < 3)
                v0 = *(const float4*)(A + (ch + 1) * 64 + (size_t)(f0 >> 4) * 256 + (f0 & 15) * 4);

            // A fragments for this ks
            const uint32_t kg2 = (uint32_t)((ks * 16 + koffA) * 2);
            uint32_t ah[2][4], al[2][4];
#pragma unroll
            for (int mf = 0; mf < 2; mf++) {
                uint32_t ad = abase + apre[mf] + (kg2 ^ axor[mf]);
                ldsm_x4(ah[mf], ad);
                ldsm_x4(al[mf], ad + 8192);
            }
            const uint32_t kc2 = (uint32_t)((ks * 16 + kcB) * 2);
#pragma unroll
            for (int gb = 0; gb < 4; gb++) {
                uint32_t bh[4], bl[4];
                uint32_t bd = wbase + bpre[gb] + (kc2 ^ bxor[gb]);
                ldsm_x4(bh, bd);
                ldsm_x4(bl, bd + 32768);
                // 3-pass interleaved: 4 independent acc chains between same-acc MMAs
#pragma unroll
                for (int mf = 0; mf < 2; mf++)
#pragma unroll
                    for (int s2 = 0; s2 < 2; s2++)
                        mma_bf16(acc[mf][gb * 2 + s2], ah[mf], &bh[s2 * 2]);
#pragma unroll
                for (int mf = 0; mf < 2; mf++)
#pragma unroll
                    for (int s2 = 0; s2 < 2; s2++)
                        mma_bf16(acc[mf][gb * 2 + s2], ah[mf], &bl[s2 * 2]);
#pragma unroll
                for (int mf = 0; mf < 2; mf++)
#pragma unroll
                    for (int s2 = 0; s2 < 2; s2++)
                        mma_bf16(acc[mf][gb * 2 + s2], al[mf], &bh[s2 * 2]);
            }

            if (ch < 3) cvt_store_a(sm, nxt, f0, v0);
        }
        __syncthreads();                          // all warps done with W chunk ch
        if (ch < 3 && tid == 0) {
            MBAR_EXPECT_TX(mb0, 65536);
            BULK_G2S(smb + SM_W, gwh + (ch + 1) * 32768, 32768, mb0);
            BULK_G2S(smb + SM_W + 32768, gwl + (ch + 1) * 32768, 32768, mb0);
        }
    }

    // ---- epilogue: stage np_j tile (64 rows, stride 260) ----
    {
        float* nps = (float*)sm;
        const float* src = g_node_p + ((size_t)b * N_SZ + jt * 64) * 256;
        int row = tid >> 2, q4 = tid & 3;
        const float4* s4 = (const float4*)(src + (size_t)row * 256) + q4 * 16;
        float4* d4 = (float4*)(nps + row * 260) + q4 * 16;
#pragma unroll
        for (int q = 0; q < 16; q++) d4[q] = s4[q];
    }
    __syncthreads();

    // per-thread bias/np_i constants (2 heads per warp, 16 cols/thread)
    float pb[16], p1[16];
    {
        const float* npi = g_node_p + ((size_t)b * N_SZ + i) * 256;
#pragma unroll
        for (int h = 0; h < 2; h++)
#pragma unroll
            for (int nf = 0; nf < 4; nf++)
#pragma unroll
                for (int v2 = 0; v2 < 2; v2++) {
                    int idx = h * 8 + nf * 2 + v2;
                    int d = wn + (h * 4 + nf) * 8 + (lane & 3) * 2 + v2;
                    float bv = bias[d];
                    pb[idx] = bv;
                    p1[idx] = bv + npi[d];
                }
    }

    const float* nps = (const float*)sm;
#pragma unroll
    for (int mf = 0; mf < 2; mf++) {
#pragma unroll
        for (int half = 0; half < 2; half++) {
            int r = wm + mf * 16 + (lane >> 2) + half * 8;
            const float* nj = nps + r * 260 + wn;
#pragma unroll
            for (int h = 0; h < 2; h++) {
                float s = 0.0f;
#pragma unroll
                for (int nf = 0; nf < 4; nf++)
#pragma unroll
                    for (int v2 = 0; v2 < 2; v2++) {
                        int idx = h * 8 + nf * 2 + v2;
                        float a = acc[mf][h * 4 + nf][half * 2 + v2];
                        float njv = nj[(h * 4 + nf) * 8 + (lane & 3) * 2 + v2];
                        s += (a + p1[idx]) * (a + pb[idx] + njv);
                    }
                s += __shfl_xor_sync(0xffffffffu, s, 1);
                s += __shfl_xor_sync(0xffffffffu, s, 2);
                if ((lane & 3) == 0) {
                    int hg = (wn >> 5) + h;
                    scores[((((size_t)b * NHEAD + hg) * N_SZ + i) << 8) + jt * 64 + r] =
                        10.0f * tanhf(s * 0.17677669529663687f);
                }
            }
        }
    }
}

// ---------------- softmax + AV (R6 exact) ----------------
__global__ void softmax_av_kernel(float* __restrict__ attn) {
    const int i = blockIdx.x, h = blockIdx.y, b = blockIdx.z;
    const int tid = threadIdx.x;
    float* row = attn + ((((size_t)(b * NHEAD + h) * N_SZ) + i) << 8);

    __shared__ float sh[16];
    __shared__ float ps[256];
    __shared__ float red[8][33];

    float s = row[tid];
    float m = s;
#pragma unroll
    for (int off = 16; off > 0; off >>= 1)
        m = fmaxf(m, __shfl_xor_sync(0xffffffffu, m, off));
    if ((tid & 31) == 0) sh[tid >> 5] = m;
    __syncthreads();
    float bm = sh[0];
#pragma unroll
    for (int g = 1; g < 8; g++) bm = fmaxf(bm, sh[g]);

    float p = __expf(s - bm);
    float t = p;
#pragma unroll
    for (int off = 16; off > 0; off >>= 1)
        t += __shfl_xor_sync(0xffffffffu, t, off);
    if ((tid & 31) == 0) sh[8 + (tid >> 5)] = t;
    __syncthreads();
    float sum = 0.0f;
#pragma unroll
    for (int g = 0; g < 8; g++) sum += sh[8 + g];

    float a = p * (1.0f / sum);
    row[tid] = a;
    ps[tid] = a;
    __syncthreads();

    const int d = tid & 31, g = tid >> 5;
    const float* np = g_node_p + (size_t)b * N_SZ * D_MODEL + h * 32 + d;
    float acc = 0.0f;
#pragma unroll
    for (int jj = 0; jj < 32; jj++) {
        int j = g * 32 + jj;
        acc = fmaf(ps[j], np[(size_t)j * 256], acc);
    }
    red[g][d] = acc;
    __syncthreads();
    if (tid < 32) {
        float o = 0.0f;
#pragma unroll
        for (int g2 = 0; g2 < 8; g2++) o += red[g2][tid];
        g_out0[((size_t)(b * N_SZ + i)) * D_MODEL + h * 32 + tid] = o;
    }
}

// ---------------- launch ----------------
extern "C" void kernel_launch(void* const* d_in, const int* in_sizes, int n_in,
                              void* d_out, int out_size) {
    const float* nodes = (const float*)d_in[0];
    const float* edges = (const float*)d_in[1];
    const float* W     = (const float*)d_in[2];
    const float* bias  = (const float*)d_in[3];

    float* out  = (float*)d_out;
    float* attn = out + B_SZ * N_SZ * D_MODEL;

    cudaFuncSetAttribute(edge_score_mma, cudaFuncAttributeMaxDynamicSharedMemorySize, SM_DYN);

    transpose_kernel<<<256, 256>>>(W);                        // 0
    wprep_kernel<<<256, 256>>>(W);                            // 1
    proj_nodes_kernel<<<(B_SZ * N_SZ) / 64, 256>>>(nodes, bias);  // 2
    dim3 g2(4, N_SZ, B_SZ);
    edge_score_mma<<<g2, NTHR, SM_DYN>>>(edges, bias, attn);  // 3 (profiled)
    dim3 g3(N_SZ, NHEAD, B_SZ);
    softmax_av_kernel<<<g3, 256>>>(attn);                     // 4
    proj_final_kernel<<<(B_SZ * N_SZ) / 64, 256>>>(bias, out);    // 5
}

// round 12
// speedup vs baseline: 1.1051x; 1.0678x over previous
#include <cuda_runtime.h>
#include <cuda_bf16.h>
#include <math.h>
#include <stdint.h>

#define D_MODEL 256
#define NHEAD   8
#define HEAD_DIM 32
#define B_SZ    4
#define N_SZ    256

// ---------------- device scratch ----------------
__device__ float g_Wt[D_MODEL * D_MODEL];
__device__ float g_node_p[B_SZ * N_SZ * D_MODEL];
__device__ float g_out0[B_SZ * N_SZ * D_MODEL];
__device__ __align__(128) unsigned char g_WB_hi[131072];
__device__ __align__(128) unsigned char g_WB_lo[131072];

__device__ __forceinline__ uint32_t smem_u32(const void* p) {
    uint32_t a;
    asm("{ .reg .u64 t; cvta.to.shared.u64 t, %1; cvt.u32.u64 %0, t; }" : "=r"(a) : "l"(p));
    return a;
}

__device__ __forceinline__ void ldsm_x4(uint32_t r[4], uint32_t addr) {
    asm volatile("ldmatrix.sync.aligned.m8n8.x4.shared.b16 {%0,%1,%2,%3}, [%4];"
                 : "=r"(r[0]), "=r"(r[1]), "=r"(r[2]), "=r"(r[3]) : "r"(addr));
}

__device__ __forceinline__ void mma_bf16(float c[4], const uint32_t a[4], const uint32_t b[2]) {
    asm volatile(
        "mma.sync.aligned.m16n8k16.row.col.f32.bf16.bf16.f32 "
        "{%0,%1,%2,%3}, {%4,%5,%6,%7}, {%8,%9}, {%0,%1,%2,%3};"
        : "+f"(c[0]), "+f"(c[1]), "+f"(c[2]), "+f"(c[3])
        : "r"(a[0]), "r"(a[1]), "r"(a[2]), "r"(a[3]), "r"(b[0]), "r"(b[1]));
}

#define MBAR_INIT(mbar, cnt) \
    asm volatile("mbarrier.init.shared.b64 [%0], %1;" :: "r"((uint32_t)(mbar)), "r"((uint32_t)(cnt)) : "memory")
#define MBAR_EXPECT_TX(mbar, tx) \
    asm volatile("mbarrier.arrive.expect_tx.shared.b64 _, [%0], %1;" :: "r"((uint32_t)(mbar)), "r"((uint32_t)(tx)) : "memory")
#define MBAR_WAIT(mbar, parity) do {                                          \
    uint32_t _m = (uint32_t)(mbar); uint32_t _p = (uint32_t)(parity);         \
    asm volatile(                                                             \
        "{\n\t.reg .pred P1;\n\t"                                             \
        "WAIT_LOOP_%=:\n\t"                                                   \
        "mbarrier.try_wait.parity.acquire.cta.shared::cta.b64 P1, [%0], %1, 0x989680;\n\t" \
        "@P1 bra.uni WAIT_DONE_%=;\n\t"                                       \
        "bra.uni WAIT_LOOP_%=;\n\t"                                           \
        "WAIT_DONE_%=:\n\t}"                                                  \
        :: "r"(_m), "r"(_p) : "memory");                                      \
} while (0)
#define BULK_G2S(dst, src, bytes, mbar) \
    asm volatile("cp.async.bulk.shared::cta.global.mbarrier::complete_tx::bytes [%0], [%1], %2, [%3];" \
                 :: "r"((uint32_t)(dst)), "l"(src), "r"((uint32_t)(bytes)), "r"((uint32_t)(mbar)) : "memory")

// ---------------- prep kernels ----------------
__global__ void transpose_kernel(const float* __restrict__ W) {
    int o = blockIdx.x * 256 + threadIdx.x;  // o = k*256 + d
    int k = o >> 8, d = o & 255;
    g_Wt[o] = W[d * 256 + k];
}

__global__ void wprep_kernel(const float* __restrict__ W) {
    int idx = blockIdx.x * 256 + threadIdx.x;  // d*256 + k
    int d = idx >> 8, k = idx & 255;
    float w = W[idx];
    __nv_bfloat16 h = __float2bfloat16_rn(w);
    float r = w - __bfloat162float(h);
    __nv_bfloat16 l = __float2bfloat16_rn(r);
    int chunk = k >> 6, kc = k & 63;
    int off = d * 128 + kc * 2;
    int sw = off ^ ((off >> 3) & 0x70);
    int pos = chunk * 32768 + sw;
    *(unsigned short*)(g_WB_hi + pos) = __bfloat16_as_ushort(h);
    *(unsigned short*)(g_WB_lo + pos) = __bfloat16_as_ushort(l);
}

// ---------------- high-occupancy projections ----------------
// 256 CTAs x 256 threads, 4 rows/CTA; device globals referenced IN-KERNEL
// (passing __device__ symbols as host-side kernel args was the R7/R8/R11 bug).
__global__ void __launch_bounds__(256, 6)
proj_nodes_simple(const float* __restrict__ A, const float* __restrict__ bias) {
    __shared__ float As[4][256];
    const int tid = threadIdx.x;
    const int r0 = blockIdx.x * 4;

#pragma unroll
    for (int q = 0; q < 4; q++)
        As[q][tid] = A[(size_t)(r0 + q) * 256 + tid];
    __syncthreads();

    float a0 = 0.0f, a1 = 0.0f, a2 = 0.0f, a3 = 0.0f;
#pragma unroll 8
    for (int k = 0; k < 256; k++) {
        float wv = g_Wt[k * 256 + tid];
        a0 = fmaf(As[0][k], wv, a0);
        a1 = fmaf(As[1][k], wv, a1);
        a2 = fmaf(As[2][k], wv, a2);
        a3 = fmaf(As[3][k], wv, a3);
    }
    float bv = bias[tid];
    g_node_p[(size_t)(r0 + 0) * 256 + tid] = a0 + bv;
    g_node_p[(size_t)(r0 + 1) * 256 + tid] = a1 + bv;
    g_node_p[(size_t)(r0 + 2) * 256 + tid] = a2 + bv;
    g_node_p[(size_t)(r0 + 3) * 256 + tid] = a3 + bv;
}

__global__ void __launch_bounds__(256, 6)
proj_final_simple(const float* __restrict__ bias, float* __restrict__ C) {
    __shared__ float As[4][256];
    const int tid = threadIdx.x;
    const int r0 = blockIdx.x * 4;

#pragma unroll
    for (int q = 0; q < 4; q++)
        As[q][tid] = g_out0[(size_t)(r0 + q) * 256 + tid];
    __syncthreads();

    float a0 = 0.0f, a1 = 0.0f, a2 = 0.0f, a3 = 0.0f;
#pragma unroll 8
    for (int k = 0; k < 256; k++) {
        float wv = g_Wt[k * 256 + tid];
        a0 = fmaf(As[0][k], wv, a0);
        a1 = fmaf(As[1][k], wv, a1);
        a2 = fmaf(As[2][k], wv, a2);
        a3 = fmaf(As[3][k], wv, a3);
    }
    float bv = bias[tid];
    C[(size_t)(r0 + 0) * 256 + tid] = a0 + bv;
    C[(size_t)(r0 + 1) * 256 + tid] = a1 + bv;
    C[(size_t)(r0 + 2) * 256 + tid] = a2 + bv;
    C[(size_t)(r0 + 3) * 256 + tid] = a3 + bv;
}

// ---------------- edge projection + scores (R10 exact) ----------------
#define SM_A   0
#define SM_W   32768
#define SM_DYN 98304
#define NTHR   256

__device__ __forceinline__ void cvt_store_a(char* sm, int slot, int flat, float4 v) {
    __nv_bfloat16 hx = __float2bfloat16_rn(v.x);
    __nv_bfloat16 hy = __float2bfloat16_rn(v.y);
    __nv_bfloat16 hz = __float2bfloat16_rn(v.z);
    __nv_bfloat16 hw = __float2bfloat16_rn(v.w);
    __nv_bfloat16 lx = __float2bfloat16_rn(v.x - __bfloat162float(hx));
    __nv_bfloat16 ly = __float2bfloat16_rn(v.y - __bfloat162float(hy));
    __nv_bfloat16 lz = __float2bfloat16_rn(v.z - __bfloat162float(hz));
    __nv_bfloat16 lw = __float2bfloat16_rn(v.w - __bfloat162float(hw));
    uint2 hi2, lo2;
    hi2.x = (uint32_t)__bfloat16_as_ushort(hx) | ((uint32_t)__bfloat16_as_ushort(hy) << 16);
    hi2.y = (uint32_t)__bfloat16_as_ushort(hz) | ((uint32_t)__bfloat16_as_ushort(hw) << 16);
    lo2.x = (uint32_t)__bfloat16_as_ushort(lx) | ((uint32_t)__bfloat16_as_ushort(ly) << 16);
    lo2.y = (uint32_t)__bfloat16_as_ushort(lz) | ((uint32_t)__bfloat16_as_ushort(lw) << 16);
    int row = flat >> 4, c4 = flat & 15;
    int off = row * 128 + c4 * 8;
    int sw = off ^ ((off >> 3) & 0x70);
    char* base = sm + SM_A + slot * 16384;
    *(uint2*)(base + sw) = hi2;
    *(uint2*)(base + 8192 + sw) = lo2;
}

__global__ void __launch_bounds__(NTHR, 2)
edge_score_mma(const float* __restrict__ edges, const float* __restrict__ bias,
               float* __restrict__ scores) {
    extern __shared__ char sm[];
    __shared__ __align__(8) unsigned long long mbarr[1];
    const uint32_t smb = smem_u32(sm);
    const uint32_t mb0 = smem_u32(&mbarr[0]);
    const int tid = threadIdx.x, wid = tid >> 5, lane = tid & 31;
    const int jt = blockIdx.x, i = blockIdx.y, b = blockIdx.z;
    const int wm = (wid >> 2) * 32;
    const int wn = (wid & 3) * 64;

    const float* A = edges + ((((size_t)b * N_SZ + i) * N_SZ) + (size_t)jt * 64) * D_MODEL;
    const unsigned long long gwh = (unsigned long long)__cvta_generic_to_global(g_WB_hi);
    const unsigned long long gwl = (unsigned long long)__cvta_generic_to_global(g_WB_lo);

    if (tid == 0) MBAR_INIT(mb0, 1);
    __syncthreads();

    if (tid == 0) {
        MBAR_EXPECT_TX(mb0, 65536);
        BULK_G2S(smb + SM_W, gwh, 32768, mb0);
        BULK_G2S(smb + SM_W + 32768, gwl, 32768, mb0);
    }
#pragma unroll
    for (int q = 0; q < 4; q++) {
        int flat = q * NTHR + tid;
        float4 v = *(const float4*)(A + (size_t)(flat >> 4) * 256 + (flat & 15) * 4);
        cvt_store_a(sm, 0, flat, v);
    }
    __syncthreads();

    float acc[2][8][4];
#pragma unroll
    for (int mf = 0; mf < 2; mf++)
#pragma unroll
        for (int nf = 0; nf < 8; nf++)
#pragma unroll
            for (int c = 0; c < 4; c++) acc[mf][nf][c] = 0.0f;

    uint32_t apre[2], axor[2];
#pragma unroll
    for (int mf = 0; mf < 2; mf++) {
        int row = wm + mf * 16 + (lane & 15);
        apre[mf] = row * 128;
        axor[mf] = (row & 7) << 4;
    }
    const int koffA = (lane >> 4) * 8;
    uint32_t bpre[4], bxor[4];
#pragma unroll
    for (int gb = 0; gb < 4; gb++) {
        int n = wn + gb * 16 + (((lane >> 3) >= 2) ? 8 : 0) + (lane & 7);
        bpre[gb] = n * 128;
        bxor[gb] = (n & 7) << 4;
    }
    const int kcB = ((lane >> 3) & 1) * 8;

#pragma unroll 1
    for (int ch = 0; ch < 4; ch++) {
        const int cur = ch & 1, nxt = cur ^ 1;
        MBAR_WAIT(mb0, ch & 1);
        const uint32_t abase = smb + SM_A + cur * 16384;
        const uint32_t wbase = smb + SM_W;

#pragma unroll
        for (int ks = 0; ks < 4; ks++) {
            float4 v0;
            int f0 = ks * NTHR + tid;
            if (ch < 3)
                v0 = *(const float4*)(A + (ch + 1) * 64 + (size_t)(f0 >> 4) * 256 + (f0 & 15) * 4);

            const uint32_t kg2 = (uint32_t)((ks * 16 + koffA) * 2);
            uint32_t ah[2][4], al[2][4];
#pragma unroll
            for (int mf = 0; mf < 2; mf++) {
                uint32_t ad = abase + apre[mf] + (kg2 ^ axor[mf]);
                ldsm_x4(ah[mf], ad);
                ldsm_x4(al[mf], ad + 8192);
            }
            const uint32_t kc2 = (uint32_t)((ks * 16 + kcB) * 2);
#pragma unroll
            for (int gb = 0; gb < 4; gb++) {
                uint32_t bh[4], bl[4];
                uint32_t bd = wbase + bpre[gb] + (kc2 ^ bxor[gb]);
                ldsm_x4(bh, bd);
                ldsm_x4(bl, bd + 32768);
#pragma unroll
                for (int mf = 0; mf < 2; mf++)
#pragma unroll
                    for (int s2 = 0; s2 < 2; s2++)
                        mma_bf16(acc[mf][gb * 2 + s2], ah[mf], &bh[s2 * 2]);
#pragma unroll
                for (int mf = 0; mf < 2; mf++)
#pragma unroll
                    for (int s2 = 0; s2 < 2; s2++)
                        mma_bf16(acc[mf][gb * 2 + s2], ah[mf], &bl[s2 * 2]);
#pragma unroll
                for (int mf = 0; mf < 2; mf++)
#pragma unroll
                    for (int s2 = 0; s2 < 2; s2++)
                        mma_bf16(acc[mf][gb * 2 + s2], al[mf], &bh[s2 * 2]);
            }

            if (ch < 3) cvt_store_a(sm, nxt, f0, v0);
        }
        __syncthreads();
        if (ch < 3 && tid == 0) {
            MBAR_EXPECT_TX(mb0, 65536);
            BULK_G2S(smb + SM_W, gwh + (ch + 1) * 32768, 32768, mb0);
            BULK_G2S(smb + SM_W + 32768, gwl + (ch + 1) * 32768, 32768, mb0);
        }
    }

    // ---- epilogue ----
    {
        float* nps = (float*)sm;
        const float* src = g_node_p + ((size_t)b * N_SZ + jt * 64) * 256;
        int row = tid >> 2, q4 = tid & 3;
        const float4* s4 = (const float4*)(src + (size_t)row * 256) + q4 * 16;
        float4* d4 = (float4*)(nps + row * 260) + q4 * 16;
#pragma unroll
        for (int q = 0; q < 16; q++) d4[q] = s4[q];
    }
    __syncthreads();

    float pb[16], p1[16];
    {
        const float* npi = g_node_p + ((size_t)b * N_SZ + i) * 256;
#pragma unroll
        for (int h = 0; h < 2; h++)
#pragma unroll
            for (int nf = 0; nf < 4; nf++)
#pragma unroll
                for (int v2 = 0; v2 < 2; v2++) {
                    int idx = h * 8 + nf * 2 + v2;
                    int d = wn + (h * 4 + nf) * 8 + (lane & 3) * 2 + v2;
                    float bv = bias[d];
                    pb[idx] = bv;
                    p1[idx] = bv + npi[d];
                }
    }

    const float* nps = (const float*)sm;
#pragma unroll
    for (int mf = 0; mf < 2; mf++) {
#pragma unroll
        for (int half = 0; half < 2; half++) {
            int r = wm + mf * 16 + (lane >> 2) + half * 8;
            const float* nj = nps + r * 260 + wn;
#pragma unroll
            for (int h = 0; h < 2; h++) {
                float s = 0.0f;
#pragma unroll
                for (int nf = 0; nf < 4; nf++)
#pragma unroll
                    for (int v2 = 0; v2 < 2; v2++) {
                        int idx = h * 8 + nf * 2 + v2;
                        float a = acc[mf][h * 4 + nf][half * 2 + v2];
                        float njv = nj[(h * 4 + nf) * 8 + (lane & 3) * 2 + v2];
                        s += (a + p1[idx]) * (a + pb[idx] + njv);
                    }
                s += __shfl_xor_sync(0xffffffffu, s, 1);
                s += __shfl_xor_sync(0xffffffffu, s, 2);
                if ((lane & 3) == 0) {
                    int hg = (wn >> 5) + h;
                    scores[((((size_t)b * NHEAD + hg) * N_SZ + i) << 8) + jt * 64 + r] =
                        10.0f * tanhf(s * 0.17677669529663687f);
                }
            }
        }
    }
}

// ---------------- softmax + AV (R6 exact) ----------------
__global__ void softmax_av_kernel(float* __restrict__ attn) {
    const int i = blockIdx.x, h = blockIdx.y, b = blockIdx.z;
    const int tid = threadIdx.x;
    float* row = attn + ((((size_t)(b * NHEAD + h) * N_SZ) + i) << 8);

    __shared__ float sh[16];
    __shared__ float ps[256];
    __shared__ float red[8][33];

    float s = row[tid];
    float m = s;
#pragma unroll
    for (int off = 16; off > 0; off >>= 1)
        m = fmaxf(m, __shfl_xor_sync(0xffffffffu, m, off));
    if ((tid & 31) == 0) sh[tid >> 5] = m;
    __syncthreads();
    float bm = sh[0];
#pragma unroll
    for (int g = 1; g < 8; g++) bm = fmaxf(bm, sh[g]);

    float p = __expf(s - bm);
    float t = p;
#pragma unroll
    for (int off = 16; off > 0; off >>= 1)
        t += __shfl_xor_sync(0xffffffffu, t, off);
    if ((tid & 31) == 0) sh[8 + (tid >> 5)] = t;
    __syncthreads();
    float sum = 0.0f;
#pragma unroll
    for (int g = 0; g < 8; g++) sum += sh[8 + g];

    float a = p * (1.0f / sum);
    row[tid] = a;
    ps[tid] = a;
    __syncthreads();

    const int d = tid & 31, g = tid >> 5;
    const float* np = g_node_p + (size_t)b * N_SZ * D_MODEL + h * 32 + d;
    float acc = 0.0f;
#pragma unroll
    for (int jj = 0; jj < 32; jj++) {
        int j = g * 32 + jj;
        acc = fmaf(ps[j], np[(size_t)j * 256], acc);
    }
    red[g][d] = acc;
    __syncthreads();
    if (tid < 32) {
        float o = 0.0f;
#pragma unroll
        for (int g2 = 0; g2 < 8; g2++) o += red[g2][tid];
        g_out0[((size_t)(b * N_SZ + i)) * D_MODEL + h * 32 + tid] = o;
    }
}

// ---------------- launch ----------------
extern "C" void kernel_launch(void* const* d_in, const int* in_sizes, int n_in,
                              void* d_out, int out_size) {
    const float* nodes = (const float*)d_in[0];
    const float* edges = (const float*)d_in[1];
    const float* W     = (const float*)d_in[2];
    const float* bias  = (const float*)d_in[3];

    float* out  = (float*)d_out;
    float* attn = out + B_SZ * N_SZ * D_MODEL;

    cudaFuncSetAttribute(edge_score_mma, cudaFuncAttributeMaxDynamicSharedMemorySize, SM_DYN);

    transpose_kernel<<<256, 256>>>(W);                          // 0
    wprep_kernel<<<256, 256>>>(W);                              // 1
    proj_nodes_simple<<<256, 256>>>(nodes, bias);               // 2
    dim3 g2(4, N_SZ, B_SZ);
    edge_score_mma<<<g2, NTHR, SM_DYN>>>(edges, bias, attn);    // 3 (profiled)
    dim3 g3(N_SZ, NHEAD, B_SZ);
    softmax_av_kernel<<<g3, 256>>>(attn);                       // 4
    proj_final_simple<<<256, 256>>>(bias, out);                 // 5
}

// round 13
// speedup vs baseline: 1.1512x; 1.0417x over previous
#include <cuda_runtime.h>
#include <cuda_bf16.h>
#include <math.h>
#include <stdint.h>

#define D_MODEL 256
#define NHEAD   8
#define HEAD_DIM 32
#define B_SZ    4
#define N_SZ    256

// ---------------- device scratch ----------------
__device__ float g_Wt[D_MODEL * D_MODEL];
__device__ float g_node_p[B_SZ * N_SZ * D_MODEL];
__device__ float g_out0[B_SZ * N_SZ * D_MODEL];
// W bf16 splits, 8 K-chunks of [256 n][32 k] bf16, 64B rows, SW64 swizzle (16KB/chunk)
__device__ __align__(128) unsigned char g_WB_hi[131072];
__device__ __align__(128) unsigned char g_WB_lo[131072];

__device__ __forceinline__ uint32_t smem_u32(const void* p) {
    uint32_t a;
    asm("{ .reg .u64 t; cvta.to.shared.u64 t, %1; cvt.u32.u64 %0, t; }" : "=r"(a) : "l"(p));
    return a;
}

__device__ __forceinline__ void ldsm_x4(uint32_t r[4], uint32_t addr) {
    asm volatile("ldmatrix.sync.aligned.m8n8.x4.shared.b16 {%0,%1,%2,%3}, [%4];"
                 : "=r"(r[0]), "=r"(r[1]), "=r"(r[2]), "=r"(r[3]) : "r"(addr));
}

__device__ __forceinline__ void mma_bf16(float c[4], const uint32_t a[4], const uint32_t b[2]) {
    asm volatile(
        "mma.sync.aligned.m16n8k16.row.col.f32.bf16.bf16.f32 "
        "{%0,%1,%2,%3}, {%4,%5,%6,%7}, {%8,%9}, {%0,%1,%2,%3};"
        : "+f"(c[0]), "+f"(c[1]), "+f"(c[2]), "+f"(c[3])
        : "r"(a[0]), "r"(a[1]), "r"(a[2]), "r"(a[3]), "r"(b[0]), "r"(b[1]));
}

#define MBAR_INIT(mbar, cnt) \
    asm volatile("mbarrier.init.shared.b64 [%0], %1;" :: "r"((uint32_t)(mbar)), "r"((uint32_t)(cnt)) : "memory")
#define MBAR_EXPECT_TX(mbar, tx) \
    asm volatile("mbarrier.arrive.expect_tx.shared.b64 _, [%0], %1;" :: "r"((uint32_t)(mbar)), "r"((uint32_t)(tx)) : "memory")
#define MBAR_WAIT(mbar, parity) do {                                          \
    uint32_t _m = (uint32_t)(mbar); uint32_t _p = (uint32_t)(parity);         \
    asm volatile(                                                             \
        "{\n\t.reg .pred P1;\n\t"                                             \
        "WAIT_LOOP_%=:\n\t"                                                   \
        "mbarrier.try_wait.parity.acquire.cta.shared::cta.b64 P1, [%0], %1, 0x989680;\n\t" \
        "@P1 bra.uni WAIT_DONE_%=;\n\t"                                       \
        "bra.uni WAIT_LOOP_%=;\n\t"                                           \
        "WAIT_DONE_%=:\n\t}"                                                  \
        :: "r"(_m), "r"(_p) : "memory");                                      \
} while (0)
#define BULK_G2S(dst, src, bytes, mbar) \
    asm volatile("cp.async.bulk.shared::cta.global.mbarrier::complete_tx::bytes [%0], [%1], %2, [%3];" \
                 :: "r"((uint32_t)(dst)), "l"(src), "r"((uint32_t)(bytes)), "r"((uint32_t)(mbar)) : "memory")

// ---------------- prep kernels ----------------
__global__ void transpose_kernel(const float* __restrict__ W) {
    int o = blockIdx.x * 256 + threadIdx.x;  // o = k*256 + d
    int k = o >> 8, d = o & 255;
    g_Wt[o] = W[d * 256 + k];
}

// 8 chunks of [256 n][32 k], 64B rows, SW64
__global__ void wprep_kernel(const float* __restrict__ W) {
    int idx = blockIdx.x * 256 + threadIdx.x;  // d*256 + k
    int d = idx >> 8, k = idx & 255;
    float w = W[idx];
    __nv_bfloat16 h = __float2bfloat16_rn(w);
    float r = w - __bfloat162float(h);
    __nv_bfloat16 l = __float2bfloat16_rn(r);
    int chunk = k >> 5, kc = k & 31;
    int off = d * 64 + kc * 2;
    int sw = off ^ ((off >> 3) & 0x30);      // SW64
    int pos = chunk * 16384 + sw;
    *(unsigned short*)(g_WB_hi + pos) = __bfloat16_as_ushort(h);
    *(unsigned short*)(g_WB_lo + pos) = __bfloat16_as_ushort(l);
}

// ---------------- high-occupancy projections (R12 exact) ----------------
__global__ void __launch_bounds__(256, 6)
proj_nodes_simple(const float* __restrict__ A, const float* __restrict__ bias) {
    __shared__ float As[4][256];
    const int tid = threadIdx.x;
    const int r0 = blockIdx.x * 4;

#pragma unroll
    for (int q = 0; q < 4; q++)
        As[q][tid] = A[(size_t)(r0 + q) * 256 + tid];
    __syncthreads();

    float a0 = 0.0f, a1 = 0.0f, a2 = 0.0f, a3 = 0.0f;
#pragma unroll 8
    for (int k = 0; k < 256; k++) {
        float wv = g_Wt[k * 256 + tid];
        a0 = fmaf(As[0][k], wv, a0);
        a1 = fmaf(As[1][k], wv, a1);
        a2 = fmaf(As[2][k], wv, a2);
        a3 = fmaf(As[3][k], wv, a3);
    }
    float bv = bias[tid];
    g_node_p[(size_t)(r0 + 0) * 256 + tid] = a0 + bv;
    g_node_p[(size_t)(r0 + 1) * 256 + tid] = a1 + bv;
    g_node_p[(size_t)(r0 + 2) * 256 + tid] = a2 + bv;
    g_node_p[(size_t)(r0 + 3) * 256 + tid] = a3 + bv;
}

__global__ void __launch_bounds__(256, 6)
proj_final_simple(const float* __restrict__ bias, float* __restrict__ C) {
    __shared__ float As[4][256];
    const int tid = threadIdx.x;
    const int r0 = blockIdx.x * 4;

#pragma unroll
    for (int q = 0; q < 4; q++)
        As[q][tid] = g_out0[(size_t)(r0 + q) * 256 + tid];
    __syncthreads();

    float a0 = 0.0f, a1 = 0.0f, a2 = 0.0f, a3 = 0.0f;
#pragma unroll 8
    for (int k = 0; k < 256; k++) {
        float wv = g_Wt[k * 256 + tid];
        a0 = fmaf(As[0][k], wv, a0);
        a1 = fmaf(As[1][k], wv, a1);
        a2 = fmaf(As[2][k], wv, a2);
        a3 = fmaf(As[3][k], wv, a3);
    }
    float bv = bias[tid];
    C[(size_t)(r0 + 0) * 256 + tid] = a0 + bv;
    C[(size_t)(r0 + 1) * 256 + tid] = a1 + bv;
    C[(size_t)(r0 + 2) * 256 + tid] = a2 + bv;
    C[(size_t)(r0 + 3) * 256 + tid] = a3 + bv;
}

// ---------------- edge projection + scores: 8 x 32-k chunks, W double-buffered ----------------
// SMEM: A slots: 2 x (4KB hi + 4KB lo)   @ 0      (16KB)
//       W slots: 2 x (16KB hi + 16KB lo) @ 16384  (64KB)
// Total 80KB -> 2 CTAs/SM.
#define SM_A   0
#define SM_W   16384
#define SM_DYN 81920
#define NTHR   256

// convert one float4 of A-chunk data (64 rows x 32 k, 64B rows, SW64)
__device__ __forceinline__ void cvt_store_a(char* sm, int slot, int flat, float4 v) {
    __nv_bfloat16 hx = __float2bfloat16_rn(v.x);
    __nv_bfloat16 hy = __float2bfloat16_rn(v.y);
    __nv_bfloat16 hz = __float2bfloat16_rn(v.z);
    __nv_bfloat16 hw = __float2bfloat16_rn(v.w);
    __nv_bfloat16 lx = __float2bfloat16_rn(v.x - __bfloat162float(hx));
    __nv_bfloat16 ly = __float2bfloat16_rn(v.y - __bfloat162float(hy));
    __nv_bfloat16 lz = __float2bfloat16_rn(v.z - __bfloat162float(hz));
    __nv_bfloat16 lw = __float2bfloat16_rn(v.w - __bfloat162float(hw));
    uint2 hi2, lo2;
    hi2.x = (uint32_t)__bfloat16_as_ushort(hx) | ((uint32_t)__bfloat16_as_ushort(hy) << 16);
    hi2.y = (uint32_t)__bfloat16_as_ushort(hz) | ((uint32_t)__bfloat16_as_ushort(hw) << 16);
    lo2.x = (uint32_t)__bfloat16_as_ushort(lx) | ((uint32_t)__bfloat16_as_ushort(ly) << 16);
    lo2.y = (uint32_t)__bfloat16_as_ushort(lz) | ((uint32_t)__bfloat16_as_ushort(lw) << 16);
    int row = flat >> 3, c4 = flat & 7;      // 8 float4 per 32-k row
    int off = row * 64 + c4 * 8;
    int sw = off ^ ((off >> 3) & 0x30);      // SW64
    char* base = sm + SM_A + slot * 8192;
    *(uint2*)(base + sw) = hi2;
    *(uint2*)(base + 4096 + sw) = lo2;
}

__global__ void __launch_bounds__(NTHR, 2)
edge_score_mma(const float* __restrict__ edges, const float* __restrict__ bias,
               float* __restrict__ scores) {
    extern __shared__ char sm[];
    __shared__ __align__(8) unsigned long long mbarr[2];
    const uint32_t smb = smem_u32(sm);
    const uint32_t mb0 = smem_u32(&mbarr[0]);
    const int tid = threadIdx.x, wid = tid >> 5, lane = tid & 31;
    const int jt = blockIdx.x, i = blockIdx.y, b = blockIdx.z;
    const int wm = (wid >> 2) * 32;
    const int wn = (wid & 3) * 64;

    const float* A = edges + ((((size_t)b * N_SZ + i) * N_SZ) + (size_t)jt * 64) * D_MODEL;
    const unsigned long long gwh = (unsigned long long)__cvta_generic_to_global(g_WB_hi);
    const unsigned long long gwl = (unsigned long long)__cvta_generic_to_global(g_WB_lo);

    if (tid == 0) { MBAR_INIT(mb0, 1); MBAR_INIT(mb0 + 8, 1); }
    __syncthreads();

    // ---- prologue: W chunk 0 (bulk, slot 0) + A chunk 0 (convert, slot 0) ----
    if (tid == 0) {
        MBAR_EXPECT_TX(mb0, 32768);
        BULK_G2S(smb + SM_W, gwh, 16384, mb0);
        BULK_G2S(smb + SM_W + 16384, gwl, 16384, mb0);
    }
#pragma unroll
    for (int q = 0; q < 2; q++) {
        int flat = q * NTHR + tid;           // 512 float4 per chunk
        float4 v = *(const float4*)(A + (size_t)(flat >> 3) * 256 + (flat & 7) * 4);
        cvt_store_a(sm, 0, flat, v);
    }
    __syncthreads();

    float acc[2][8][4];
#pragma unroll
    for (int mf = 0; mf < 2; mf++)
#pragma unroll
        for (int nf = 0; nf < 8; nf++)
#pragma unroll
            for (int c = 0; c < 4; c++) acc[mf][nf][c] = 0.0f;

    uint32_t apre[2], axor[2];
#pragma unroll
    for (int mf = 0; mf < 2; mf++) {
        int row = wm + mf * 16 + (lane & 15);
        apre[mf] = row * 64;
        axor[mf] = (row & 6) << 3;           // SW64
    }
    const int koffA = (lane >> 4) * 8;
    uint32_t bpre[4], bxor[4];
#pragma unroll
    for (int gb = 0; gb < 4; gb++) {
        int n = wn + gb * 16 + (((lane >> 3) >= 2) ? 8 : 0) + (lane & 7);
        bpre[gb] = n * 64;
        bxor[gb] = (n & 6) << 3;             // SW64
    }
    const int kcB = ((lane >> 3) & 1) * 8;

#pragma unroll 1
    for (int ch = 0; ch < 8; ch++) {
        const int cur = ch & 1, nxt = cur ^ 1;
        // issue next W chunk into the OTHER slot before waiting/computing (overlap)
        if (ch < 7 && tid == 0) {
            MBAR_EXPECT_TX(mb0 + 8 * nxt, 32768);
            BULK_G2S(smb + SM_W + nxt * 32768, gwh + (ch + 1) * 16384, 16384, mb0 + 8 * nxt);
            BULK_G2S(smb + SM_W + nxt * 32768 + 16384, gwl + (ch + 1) * 16384, 16384, mb0 + 8 * nxt);
        }
        MBAR_WAIT(mb0 + 8 * cur, (ch >> 1) & 1);

        const uint32_t abase = smb + SM_A + cur * 8192;
        const uint32_t wbase = smb + SM_W + cur * 32768;

#pragma unroll
        for (int ks = 0; ks < 2; ks++) {
            // prefetch next-chunk A fp32 (1 float4/thread/ks)
            float4 v0;
            int f0 = ks * NTHR + tid;
            if (ch < 7)
                v0 = *(const float4*)(A + (ch + 1) * 32 + (size_t)(f0 >> 3) * 256 + (f0 & 7) * 4);

            const uint32_t kg2 = (uint32_t)((ks * 16 + koffA) * 2);
            uint32_t ah[2][4], al[2][4];
#pragma unroll
            for (int mf = 0; mf < 2; mf++) {
                uint32_t ad = abase + apre[mf] + (kg2 ^ axor[mf]);
                ldsm_x4(ah[mf], ad);
                ldsm_x4(al[mf], ad + 4096);
            }
            const uint32_t kc2 = (uint32_t)((ks * 16 + kcB) * 2);
#pragma unroll
            for (int gb = 0; gb < 4; gb++) {
                uint32_t bh[4], bl[4];
                uint32_t bd = wbase + bpre[gb] + (kc2 ^ bxor[gb]);
                ldsm_x4(bh, bd);
                ldsm_x4(bl, bd + 16384);
#pragma unroll
                for (int mf = 0; mf < 2; mf++)
#pragma unroll
                    for (int s2 = 0; s2 < 2; s2++)
                        mma_bf16(acc[mf][gb * 2 + s2], ah[mf], &bh[s2 * 2]);
#pragma unroll
                for (int mf = 0; mf < 2; mf++)
#pragma unroll
                    for (int s2 = 0; s2 < 2; s2++)
                        mma_bf16(acc[mf][gb * 2 + s2], ah[mf], &bl[s2 * 2]);
#pragma unroll
                for (int mf = 0; mf < 2; mf++)
#pragma unroll
                    for (int s2 = 0; s2 < 2; s2++)
                        mma_bf16(acc[mf][gb * 2 + s2], al[mf], &bh[s2 * 2]);
            }

            if (ch < 7) cvt_store_a(sm, nxt, f0, v0);
        }
        __syncthreads();   // all warps done with W[cur] + A[cur]; A[nxt] writes visible
    }

    // ---- epilogue (R10/R12 exact) ----
    {
        float* nps = (float*)sm;
        const float* src = g_node_p + ((size_t)b * N_SZ + jt * 64) * 256;
        int row = tid >> 2, q4 = tid & 3;
        const float4* s4 = (const float4*)(src + (size_t)row * 256) + q4 * 16;
        float4* d4 = (float4*)(nps + row * 260) + q4 * 16;
#pragma unroll
        for (int q = 0; q < 16; q++) d4[q] = s4[q];
    }
    __syncthreads();

    float pb[16], p1[16];
    {
        const float* npi = g_node_p + ((size_t)b * N_SZ + i) * 256;
#pragma unroll
        for (int h = 0; h < 2; h++)
#pragma unroll
            for (int nf = 0; nf < 4; nf++)
#pragma unroll
                for (int v2 = 0; v2 < 2; v2++) {
                    int idx = h * 8 + nf * 2 + v2;
                    int d = wn + (h * 4 + nf) * 8 + (lane & 3) * 2 + v2;
                    float bv = bias[d];
                    pb[idx] = bv;
                    p1[idx] = bv + npi[d];
                }
    }

    const float* nps = (const float*)sm;
#pragma unroll
    for (int mf = 0; mf < 2; mf++) {
#pragma unroll
        for (int half = 0; half < 2; half++) {
            int r = wm + mf * 16 + (lane >> 2) + half * 8;
            const float* nj = nps + r * 260 + wn;
#pragma unroll
            for (int h = 0; h < 2; h++) {
                float s = 0.0f;
#pragma unroll
                for (int nf = 0; nf < 4; nf++)
#pragma unroll
                    for (int v2 = 0; v2 < 2; v2++) {
                        int idx = h * 8 + nf * 2 + v2;
                        float a = acc[mf][h * 4 + nf][half * 2 + v2];
                        float njv = nj[(h * 4 + nf) * 8 + (lane & 3) * 2 + v2];
                        s += (a + p1[idx]) * (a + pb[idx] + njv);
                    }
                s += __shfl_xor_sync(0xffffffffu, s, 1);
                s += __shfl_xor_sync(0xffffffffu, s, 2);
                if ((lane & 3) == 0) {
                    int hg = (wn >> 5) + h;
                    scores[((((size_t)b * NHEAD + hg) * N_SZ + i) << 8) + jt * 64 + r] =
                        10.0f * tanhf(s * 0.17677669529663687f);
                }
            }
        }
    }
}

// ---------------- softmax + AV (R6 exact) ----------------
__global__ void softmax_av_kernel(float* __restrict__ attn) {
    const int i = blockIdx.x, h = blockIdx.y, b = blockIdx.z;
    const int tid = threadIdx.x;
    float* row = attn + ((((size_t)(b * NHEAD + h) * N_SZ) + i) << 8);

    __shared__ float sh[16];
    __shared__ float ps[256];
    __shared__ float red[8][33];

    float s = row[tid];
    float m = s;
#pragma unroll
    for (int off = 16; off > 0; off >>= 1)
        m = fmaxf(m, __shfl_xor_sync(0xffffffffu, m, off));
    if ((tid & 31) == 0) sh[tid >> 5] = m;
    __syncthreads();
    float bm = sh[0];
#pragma unroll
    for (int g = 1; g < 8; g++) bm = fmaxf(bm, sh[g]);

    float p = __expf(s - bm);
    float t = p;
#pragma unroll
    for (int off = 16; off > 0; off >>= 1)
        t += __shfl_xor_sync(0xffffffffu, t, off);
    if ((tid & 31) == 0) sh[8 + (tid >> 5)] = t;
    __syncthreads();
    float sum = 0.0f;
#pragma unroll
    for (int g = 0; g < 8; g++) sum += sh[8 + g];

    float a = p * (1.0f / sum);
    row[tid] = a;
    ps[tid] = a;
    __syncthreads();

    const int d = tid & 31, g = tid >> 5;
    const float* np = g_node_p + (size_t)b * N_SZ * D_MODEL + h * 32 + d;
    float acc = 0.0f;
#pragma unroll
    for (int jj = 0; jj < 32; jj++) {
        int j = g * 32 + jj;
        acc = fmaf(ps[j], np[(size_t)j * 256], acc);
    }
    red[g][d] = acc;
    __syncthreads();
    if (tid < 32) {
        float o = 0.0f;
#pragma unroll
        for (int g2 = 0; g2 < 8; g2++) o += red[g2][tid];
        g_out0[((size_t)(b * N_SZ + i)) * D_MODEL + h * 32 + tid] = o;
    }
}

// ---------------- launch ----------------
extern "C" void kernel_launch(void* const* d_in, const int* in_sizes, int n_in,
                              void* d_out, int out_size) {
    const float* nodes = (const float*)d_in[0];
    const float* edges = (const float*)d_in[1];
    const float* W     = (const float*)d_in[2];
    const float* bias  = (const float*)d_in[3];

    float* out  = (float*)d_out;
    float* attn = out + B_SZ * N_SZ * D_MODEL;

    cudaFuncSetAttribute(edge_score_mma, cudaFuncAttributeMaxDynamicSharedMemorySize, SM_DYN);

    transpose_kernel<<<256, 256>>>(W);                          // 0
    wprep_kernel<<<256, 256>>>(W);                              // 1
    proj_nodes_simple<<<256, 256>>>(nodes, bias);               // 2
    dim3 g2(4, N_SZ, B_SZ);
    edge_score_mma<<<g2, NTHR, SM_DYN>>>(edges, bias, attn);    // 3 (profiled)
    dim3 g3(N_SZ, NHEAD, B_SZ);
    softmax_av_kernel<<<g3, 256>>>(attn);                       // 4
    proj_final_simple<<<256, 256>>>(bias, out);                 // 5
}